// round 1
// baseline (speedup 1.0000x reference)
#include <cuda_runtime.h>

#define NN 100000
#define EE 3200000
#define GG 100
#define HH 48

// ---------------- device scratch (static: no allocations allowed) ----------------
__device__ float g_deg[NN];        // out-degree (segment_sum over src)
__device__ float g_dis[NN];        // deg^-1/2 (0 if deg==0)
__device__ float g_diag[NN];       // 2/lmax[batch[n]] - 1
__device__ int   g_cnt[NN];        // in-degree counters (CSR build)
__device__ int   g_rowptr[NN + 1]; // CSR row pointers by dst
__device__ int   g_csrc[EE];       // CSR column (src node) per edge, grouped by dst
__device__ float g_wedge[EE];      // edge weight, aligned with g_csrc
__device__ float g_T1[NN * HH];
__device__ float g_T2[NN * HH];
__device__ float g_T3[NN * HH];
__device__ float g_T4[NN * HH];
__device__ float g_hA[NN * HH];
__device__ float g_hB[NN * HH];

// ---------------- graph preprocessing ----------------
__global__ void k_degree(const int* __restrict__ src, const int* __restrict__ dst) {
    int e = blockIdx.x * blockDim.x + threadIdx.x;
    if (e >= EE) return;
    atomicAdd(&g_deg[src[e]], 1.0f);
    atomicAdd(&g_cnt[dst[e]], 1);
}

__global__ void k_node(const int* __restrict__ batch, const float* __restrict__ lmax) {
    int n = blockIdx.x * blockDim.x + threadIdx.x;
    if (n >= NN) return;
    float d = g_deg[n];
    g_dis[n] = (d > 0.0f) ? rsqrtf(d) : 0.0f;
    g_diag[n] = 2.0f / lmax[batch[n]] - 1.0f;
}

// single-block exclusive scan of g_cnt -> g_rowptr (N = 100k, chunked over 1024 threads)
__global__ void k_scan() {
    __shared__ int sums[1024];
    const int tid = threadIdx.x;
    const int CH = (NN + 1023) / 1024;
    int start = tid * CH;
    int end = start + CH; if (end > NN) end = NN; if (start > NN) start = NN;
    int s = 0;
    for (int i = start; i < end; i++) s += g_cnt[i];
    sums[tid] = s;
    __syncthreads();
    // Hillis-Steele inclusive scan
    for (int off = 1; off < 1024; off <<= 1) {
        int v = (tid >= off) ? sums[tid - off] : 0;
        __syncthreads();
        sums[tid] += v;
        __syncthreads();
    }
    int run = sums[tid] - s;  // exclusive prefix for this chunk
    for (int i = start; i < end; i++) {
        g_rowptr[i] = run;
        run += g_cnt[i];
    }
    if (tid == 1023) g_rowptr[NN] = run;  // == EE
}

__global__ void k_fill(const int* __restrict__ src, const int* __restrict__ dst,
                       const int* __restrict__ batch, const float* __restrict__ lmax) {
    int e = blockIdx.x * blockDim.x + threadIdx.x;
    if (e >= EE) return;
    int s = src[e], d = dst[e];
    int pos = g_rowptr[d] + atomicAdd(&g_cnt[d], 1);
    g_csrc[pos] = s;
    g_wedge[pos] = -2.0f * g_dis[s] * g_dis[d] / lmax[batch[s]];
}

// ---------------- Chebyshev propagation: warp-per-node CSR gather ----------------
// tout[n] = alpha * (diag[n]*tin[n] + sum_e wedge[e]*tin[csrc[e]])  (+ (-1)*tprev[n] if HASPREV)
template <int F, bool HASPREV>
__global__ void k_prop(const float* __restrict__ tin, const float* __restrict__ tprev,
                       float* __restrict__ tout, float alpha) {
    int n = (blockIdx.x * blockDim.x + threadIdx.x) >> 5;
    if (n >= NN) return;
    int lane = threadIdx.x & 31;
    int beg = g_rowptr[n], end = g_rowptr[n + 1];
    float acc0 = 0.0f, acc1 = 0.0f;
    int e = beg;
    for (; e + 1 < end; e += 2) {
        int s0 = g_csrc[e];     float w0 = g_wedge[e];
        int s1 = g_csrc[e + 1]; float w1 = g_wedge[e + 1];
        if (F == 48) {
            float a0 = tin[s0 * 48 + lane];
            float a1 = tin[s1 * 48 + lane];
            float b0 = (lane < 16) ? tin[s0 * 48 + 32 + lane] : 0.0f;
            float b1 = (lane < 16) ? tin[s1 * 48 + 32 + lane] : 0.0f;
            acc0 += w0 * a0 + w1 * a1;
            acc1 += w0 * b0 + w1 * b1;
        } else {
            float a0 = (lane < 16) ? tin[s0 * 16 + lane] : 0.0f;
            float a1 = (lane < 16) ? tin[s1 * 16 + lane] : 0.0f;
            acc0 += w0 * a0 + w1 * a1;
        }
    }
    if (e < end) {
        int s0 = g_csrc[e]; float w0 = g_wedge[e];
        if (F == 48) {
            acc0 += w0 * tin[s0 * 48 + lane];
            if (lane < 16) acc1 += w0 * tin[s0 * 48 + 32 + lane];
        } else {
            if (lane < 16) acc0 += w0 * tin[s0 * 16 + lane];
        }
    }
    float dg = g_diag[n];
    if (F == 48) {
        float r0 = alpha * (dg * tin[n * 48 + lane] + acc0);
        if (HASPREV) r0 -= tprev[n * 48 + lane];
        tout[n * 48 + lane] = r0;
        if (lane < 16) {
            float r1 = alpha * (dg * tin[n * 48 + 32 + lane] + acc1);
            if (HASPREV) r1 -= tprev[n * 48 + 32 + lane];
            tout[n * 48 + 32 + lane] = r1;
        }
    } else {
        if (lane < 16) {
            float r0 = alpha * (dg * tin[n * 16 + lane] + acc0);
            if (HASPREV) r0 -= tprev[n * 16 + lane];
            tout[n * 16 + lane] = r0;
        }
    }
}

// ---------------- fused layer output: h = relu(b + sum_k T_k @ W[k]) ----------------
// Thread computes one node's 4 consecutive output features (float4).
template <int FIN>
__global__ void k_mix(const float* __restrict__ T0, const float* __restrict__ T1,
                      const float* __restrict__ T2, const float* __restrict__ T3,
                      const float* __restrict__ T4,
                      const float* __restrict__ W, const float* __restrict__ b,
                      float* __restrict__ hout) {
    __shared__ __align__(16) float sW[5 * FIN * 48];
    const int tot = 5 * FIN * 48;
    for (int i = threadIdx.x; i < tot; i += blockDim.x) sW[i] = W[i];
    __syncthreads();
    int gid = blockIdx.x * blockDim.x + threadIdx.x;
    int n = gid / 12;
    int f = (gid % 12) * 4;
    if (n >= NN) return;
    const float* Ts[5] = {T0, T1, T2, T3, T4};
    float4 acc = *reinterpret_cast<const float4*>(&b[f]);
#pragma unroll
    for (int k = 0; k < 5; k++) {
        const float* T = Ts[k] + n * FIN;
        const float* wk = &sW[k * FIN * 48 + f];
#pragma unroll
        for (int i = 0; i < FIN; i++) {
            float v = T[i];
            float4 wv = *reinterpret_cast<const float4*>(wk + i * 48);
            acc.x += v * wv.x;
            acc.y += v * wv.y;
            acc.z += v * wv.z;
            acc.w += v * wv.w;
        }
    }
    acc.x = fmaxf(acc.x, 0.0f);
    acc.y = fmaxf(acc.y, 0.0f);
    acc.z = fmaxf(acc.z, 0.0f);
    acc.w = fmaxf(acc.w, 0.0f);
    *reinterpret_cast<float4*>(&hout[n * 48 + f]) = acc;
}

// ---------------- global_add_pool + MLP head (batch = contiguous 1000-node blocks) ----
__global__ void k_pool(const float* __restrict__ h,
                       const float* __restrict__ fc1w, const float* __restrict__ fc1b,
                       const float* __restrict__ fc2w, const float* __restrict__ fc2b,
                       float* __restrict__ out) {
    const int g = blockIdx.x;
    const int tid = threadIdx.x;  // 480 threads: r = tid/48 (0..9), f = tid%48
    const int r = tid / 48, f = tid % 48;
    const int base = g * (NN / GG);
    float a = 0.0f;
    for (int n = base + r; n < base + (NN / GG); n += 10) a += h[n * 48 + f];
    __shared__ float red[480];
    __shared__ float pooled[48];
    __shared__ float o1[32];
    red[tid] = a;
    __syncthreads();
    if (tid < 48) {
        float s = 0.0f;
        for (int rr = 0; rr < 10; rr++) s += red[rr * 48 + tid];
        pooled[tid] = s;
    }
    __syncthreads();
    if (tid < 32) {
        float s = fc1b[tid];
        for (int i = 0; i < 48; i++) s += pooled[i] * fc1w[i * 32 + tid];
        o1[tid] = fmaxf(s, 0.0f);
    }
    __syncthreads();
    if (tid == 0) {
        float s = fc2b[0];
        for (int j = 0; j < 32; j++) s += o1[j] * fc2w[j];
        out[g] = s;
    }
}

// ---------------- host launcher ----------------
extern "C" void kernel_launch(void* const* d_in, const int* in_sizes, int n_in,
                              void* d_out, int out_size) {
    const float* x     = (const float*)d_in[0];
    const int*   ei    = (const int*)d_in[1];
    const int*   src   = ei;
    const int*   dst   = ei + EE;
    const int*   batch = (const int*)d_in[2];
    const float* lmax  = (const float*)d_in[3];
    const float* W[5]  = {(const float*)d_in[4], (const float*)d_in[6], (const float*)d_in[8],
                          (const float*)d_in[10], (const float*)d_in[12]};
    const float* B[5]  = {(const float*)d_in[5], (const float*)d_in[7], (const float*)d_in[9],
                          (const float*)d_in[11], (const float*)d_in[13]};
    const float* fc1w = (const float*)d_in[14];
    const float* fc1b = (const float*)d_in[15];
    const float* fc2w = (const float*)d_in[16];
    const float* fc2b = (const float*)d_in[17];
    float* out = (float*)d_out;

    void* p;
    cudaGetSymbolAddress(&p, g_deg); float* deg = (float*)p;
    cudaGetSymbolAddress(&p, g_cnt); int* cnt = (int*)p;
    cudaGetSymbolAddress(&p, g_T1); float* T1 = (float*)p;
    cudaGetSymbolAddress(&p, g_T2); float* T2 = (float*)p;
    cudaGetSymbolAddress(&p, g_T3); float* T3 = (float*)p;
    cudaGetSymbolAddress(&p, g_T4); float* T4 = (float*)p;
    cudaGetSymbolAddress(&p, g_hA); float* hA = (float*)p;
    cudaGetSymbolAddress(&p, g_hB); float* hB = (float*)p;

    cudaMemsetAsync(deg, 0, NN * sizeof(float), 0);
    cudaMemsetAsync(cnt, 0, NN * sizeof(int), 0);
    k_degree<<<(EE + 255) / 256, 256>>>(src, dst);
    k_node<<<(NN + 255) / 256, 256>>>(batch, lmax);
    k_scan<<<1, 1024>>>();
    cudaMemsetAsync(cnt, 0, NN * sizeof(int), 0);
    k_fill<<<(EE + 255) / 256, 256>>>(src, dst, batch, lmax);

    const int PB = 256;
    const int pgrid = (NN * 32 + PB - 1) / PB;   // warp per node
    const int mgrid = (NN * 12 + 255) / 256;     // thread per (node, 4-feature group)

    // layer 1 (F_in = 16, T0 = x)
    k_prop<16, false><<<pgrid, PB>>>(x, nullptr, T1, 1.0f);
    k_prop<16, true><<<pgrid, PB>>>(T1, x, T2, 2.0f);
    k_prop<16, true><<<pgrid, PB>>>(T2, T1, T3, 2.0f);
    k_prop<16, true><<<pgrid, PB>>>(T3, T2, T4, 2.0f);
    k_mix<16><<<mgrid, 256>>>(x, T1, T2, T3, T4, W[0], B[0], hA);

    // layers 2..5 (F_in = 48), ping-pong hA <-> hB
    float* cur = hA;
    float* nxt = hB;
    for (int l = 1; l < 5; l++) {
        k_prop<48, false><<<pgrid, PB>>>(cur, nullptr, T1, 1.0f);
        k_prop<48, true><<<pgrid, PB>>>(T1, cur, T2, 2.0f);
        k_prop<48, true><<<pgrid, PB>>>(T2, T1, T3, 2.0f);
        k_prop<48, true><<<pgrid, PB>>>(T3, T2, T4, 2.0f);
        k_mix<48><<<mgrid, 256>>>(cur, T1, T2, T3, T4, W[l], B[l], nxt);
        float* t = cur; cur = nxt; nxt = t;
    }

    k_pool<<<GG, 480>>>(cur, fc1w, fc1b, fc2w, fc2b, out);
}

// round 2
// speedup vs baseline: 1.2306x; 1.2306x over previous
#include <cuda_runtime.h>
#include <cuda_fp16.h>

#define NN 100000
#define EE 3200000
#define GG 100
#define HH 48

// ---------------- device scratch (static: no allocations allowed) ----------------
__device__ float g_deg[NN];
__device__ float g_dis[NN];
__device__ float g_diag[NN];
__device__ int   g_cnt[NN];
__device__ int   g_rowptr[NN + 1];
__device__ int2  g_edge[EE];          // {src, wedge as float bits}, grouped by dst
__device__ __half g_x16[NN * 16];     // layer-1 input in fp16
__device__ __half g_T1[NN * HH];
__device__ __half g_T2[NN * HH];
__device__ __half g_T3[NN * HH];
__device__ __half g_T4[NN * HH];
__device__ __half g_hA[NN * HH];
__device__ __half g_hB[NN * HH];

// ---------------- graph preprocessing ----------------
__global__ void k_degree(const int* __restrict__ src, const int* __restrict__ dst) {
    int e = blockIdx.x * blockDim.x + threadIdx.x;
    if (e >= EE) return;
    atomicAdd(&g_deg[src[e]], 1.0f);
    atomicAdd(&g_cnt[dst[e]], 1);
}

__global__ void k_node(const int* __restrict__ batch, const float* __restrict__ lmax) {
    int n = blockIdx.x * blockDim.x + threadIdx.x;
    if (n >= NN) return;
    float d = g_deg[n];
    g_dis[n] = (d > 0.0f) ? rsqrtf(d) : 0.0f;
    g_diag[n] = 2.0f / lmax[batch[n]] - 1.0f;
}

// single-block exclusive scan of g_cnt -> g_rowptr
__global__ void k_scan() {
    __shared__ int sums[1024];
    const int tid = threadIdx.x;
    const int CH = (NN + 1023) / 1024;
    int start = tid * CH;
    int end = start + CH; if (end > NN) end = NN; if (start > NN) start = NN;
    int s = 0;
    for (int i = start; i < end; i++) s += g_cnt[i];
    sums[tid] = s;
    __syncthreads();
    for (int off = 1; off < 1024; off <<= 1) {
        int v = (tid >= off) ? sums[tid - off] : 0;
        __syncthreads();
        sums[tid] += v;
        __syncthreads();
    }
    int run = sums[tid] - s;
    for (int i = start; i < end; i++) {
        g_rowptr[i] = run;
        run += g_cnt[i];
    }
    if (tid == 1023) g_rowptr[NN] = run;
}

__global__ void k_fill(const int* __restrict__ src, const int* __restrict__ dst,
                       const float* __restrict__ lmax) {
    int e = blockIdx.x * blockDim.x + threadIdx.x;
    if (e >= EE) return;
    int s = src[e], d = dst[e];
    int pos = g_rowptr[d] + atomicAdd(&g_cnt[d], 1);
    float w = -2.0f * g_dis[s] * g_dis[d] / lmax[s / (NN / GG)];
    g_edge[pos] = make_int2(s, __float_as_int(w));
}

__global__ void k_xcast(const float* __restrict__ x) {
    int i = blockIdx.x * blockDim.x + threadIdx.x;   // one half2 per thread
    if (i >= NN * 8) return;
    float2 v = reinterpret_cast<const float2*>(x)[i];
    reinterpret_cast<__half2*>(g_x16)[i] = __floats2half2_rn(v.x, v.y);
}

// ---------------- Chebyshev propagation (fp16 features, fp32 accumulate) -------------
// F = 16: 8 lanes per node, each lane owns one half2 column pair.
template <bool HASPREV>
__global__ void k_prop16(const __half2* __restrict__ tin, const __half2* __restrict__ tprev,
                         __half2* __restrict__ tout, float alpha) {
    int t = blockIdx.x * blockDim.x + threadIdx.x;
    int n = t >> 3;
    if (n >= NN) return;
    int lane = t & 7;
    int beg = g_rowptr[n], end = g_rowptr[n + 1];
    float ax = 0.0f, ay = 0.0f;
    int e = beg;
    for (; e + 1 < end; e += 2) {
        int2 E0 = g_edge[e];
        int2 E1 = g_edge[e + 1];
        float w0 = __int_as_float(E0.y), w1 = __int_as_float(E1.y);
        float2 f0 = __half22float2(tin[E0.x * 8 + lane]);
        float2 f1 = __half22float2(tin[E1.x * 8 + lane]);
        ax += w0 * f0.x + w1 * f1.x;
        ay += w0 * f0.y + w1 * f1.y;
    }
    if (e < end) {
        int2 E0 = g_edge[e];
        float w0 = __int_as_float(E0.y);
        float2 f0 = __half22float2(tin[E0.x * 8 + lane]);
        ax += w0 * f0.x;
        ay += w0 * f0.y;
    }
    float dg = g_diag[n];
    float2 fs = __half22float2(tin[n * 8 + lane]);
    float rx = alpha * (dg * fs.x + ax);
    float ry = alpha * (dg * fs.y + ay);
    if (HASPREV) {
        float2 fp = __half22float2(tprev[n * 8 + lane]);
        rx -= fp.x; ry -= fp.y;
    }
    tout[n * 8 + lane] = __floats2half2_rn(rx, ry);
}

// F = 48: warp per node, lanes 0..23 own half2 column pairs.
template <bool HASPREV>
__global__ void k_prop48(const __half2* __restrict__ tin, const __half2* __restrict__ tprev,
                         __half2* __restrict__ tout, float alpha) {
    int n = (blockIdx.x * blockDim.x + threadIdx.x) >> 5;
    if (n >= NN) return;
    int lane = threadIdx.x & 31;
    int beg = g_rowptr[n], end = g_rowptr[n + 1];
    float ax = 0.0f, ay = 0.0f;
    int e = beg;
    for (; e + 1 < end; e += 2) {
        int2 E0 = g_edge[e];
        int2 E1 = g_edge[e + 1];
        float w0 = __int_as_float(E0.y), w1 = __int_as_float(E1.y);
        if (lane < 24) {
            float2 f0 = __half22float2(tin[E0.x * 24 + lane]);
            float2 f1 = __half22float2(tin[E1.x * 24 + lane]);
            ax += w0 * f0.x + w1 * f1.x;
            ay += w0 * f0.y + w1 * f1.y;
        }
    }
    if (e < end) {
        int2 E0 = g_edge[e];
        float w0 = __int_as_float(E0.y);
        if (lane < 24) {
            float2 f0 = __half22float2(tin[E0.x * 24 + lane]);
            ax += w0 * f0.x;
            ay += w0 * f0.y;
        }
    }
    if (lane < 24) {
        float dg = g_diag[n];
        float2 fs = __half22float2(tin[n * 24 + lane]);
        float rx = alpha * (dg * fs.x + ax);
        float ry = alpha * (dg * fs.y + ay);
        if (HASPREV) {
            float2 fp = __half22float2(tprev[n * 24 + lane]);
            rx -= fp.x; ry -= fp.y;
        }
        tout[n * 24 + lane] = __floats2half2_rn(rx, ry);
    }
}

// ---------------- fused layer output: h = relu(b + sum_k T_k @ W[k]) ----------------
template <int FIN>
__global__ void k_mix(const __half2* __restrict__ T0, const __half2* __restrict__ T1,
                      const __half2* __restrict__ T2, const __half2* __restrict__ T3,
                      const __half2* __restrict__ T4,
                      const float* __restrict__ W, const float* __restrict__ b,
                      __half2* __restrict__ hout) {
    __shared__ __align__(16) float sW[5 * FIN * 48];
    const int tot = 5 * FIN * 48;
    for (int i = threadIdx.x; i < tot; i += blockDim.x) sW[i] = W[i];
    __syncthreads();
    int gid = blockIdx.x * blockDim.x + threadIdx.x;
    int n = gid / 12;
    int f = (gid % 12) * 4;
    if (n >= NN) return;
    const __half2* Ts[5] = {T0, T1, T2, T3, T4};
    float4 acc = *reinterpret_cast<const float4*>(&b[f]);
#pragma unroll
    for (int k = 0; k < 5; k++) {
        const __half2* T = Ts[k] + n * (FIN / 2);
        const float* wk = &sW[k * FIN * 48 + f];
#pragma unroll
        for (int i2 = 0; i2 < FIN / 2; i2++) {
            float2 v = __half22float2(T[i2]);
            float4 w0 = *reinterpret_cast<const float4*>(wk + (2 * i2) * 48);
            float4 w1 = *reinterpret_cast<const float4*>(wk + (2 * i2 + 1) * 48);
            acc.x += v.x * w0.x + v.y * w1.x;
            acc.y += v.x * w0.y + v.y * w1.y;
            acc.z += v.x * w0.z + v.y * w1.z;
            acc.w += v.x * w0.w + v.y * w1.w;
        }
    }
    acc.x = fmaxf(acc.x, 0.0f);
    acc.y = fmaxf(acc.y, 0.0f);
    acc.z = fmaxf(acc.z, 0.0f);
    acc.w = fmaxf(acc.w, 0.0f);
    hout[n * 24 + f / 2]     = __floats2half2_rn(acc.x, acc.y);
    hout[n * 24 + f / 2 + 1] = __floats2half2_rn(acc.z, acc.w);
}

// ---------------- global_add_pool + MLP head ----------------
__global__ void k_pool(const __half* __restrict__ h,
                       const float* __restrict__ fc1w, const float* __restrict__ fc1b,
                       const float* __restrict__ fc2w, const float* __restrict__ fc2b,
                       float* __restrict__ out) {
    const int g = blockIdx.x;
    const int tid = threadIdx.x;  // 480 threads: r = tid/48 (0..9), f = tid%48
    const int r = tid / 48, f = tid % 48;
    const int base = g * (NN / GG);
    float a = 0.0f;
    for (int n = base + r; n < base + (NN / GG); n += 10) a += __half2float(h[n * 48 + f]);
    __shared__ float red[480];
    __shared__ float pooled[48];
    __shared__ float o1[32];
    red[tid] = a;
    __syncthreads();
    if (tid < 48) {
        float s = 0.0f;
        for (int rr = 0; rr < 10; rr++) s += red[rr * 48 + tid];
        pooled[tid] = s;
    }
    __syncthreads();
    if (tid < 32) {
        float s = fc1b[tid];
        for (int i = 0; i < 48; i++) s += pooled[i] * fc1w[i * 32 + tid];
        o1[tid] = fmaxf(s, 0.0f);
    }
    __syncthreads();
    if (tid == 0) {
        float s = fc2b[0];
        for (int j = 0; j < 32; j++) s += o1[j] * fc2w[j];
        out[g] = s;
    }
}

// ---------------- host launcher ----------------
extern "C" void kernel_launch(void* const* d_in, const int* in_sizes, int n_in,
                              void* d_out, int out_size) {
    const float* x     = (const float*)d_in[0];
    const int*   ei    = (const int*)d_in[1];
    const int*   src   = ei;
    const int*   dst   = ei + EE;
    const int*   batch = (const int*)d_in[2];
    const float* lmax  = (const float*)d_in[3];
    const float* W[5]  = {(const float*)d_in[4], (const float*)d_in[6], (const float*)d_in[8],
                          (const float*)d_in[10], (const float*)d_in[12]};
    const float* B[5]  = {(const float*)d_in[5], (const float*)d_in[7], (const float*)d_in[9],
                          (const float*)d_in[11], (const float*)d_in[13]};
    const float* fc1w = (const float*)d_in[14];
    const float* fc1b = (const float*)d_in[15];
    const float* fc2w = (const float*)d_in[16];
    const float* fc2b = (const float*)d_in[17];
    float* out = (float*)d_out;

    void* p;
    cudaGetSymbolAddress(&p, g_deg);  float* deg = (float*)p;
    cudaGetSymbolAddress(&p, g_cnt);  int* cnt = (int*)p;
    cudaGetSymbolAddress(&p, g_x16);  __half2* x16 = (__half2*)p;
    cudaGetSymbolAddress(&p, g_T1);   __half2* T1 = (__half2*)p;
    cudaGetSymbolAddress(&p, g_T2);   __half2* T2 = (__half2*)p;
    cudaGetSymbolAddress(&p, g_T3);   __half2* T3 = (__half2*)p;
    cudaGetSymbolAddress(&p, g_T4);   __half2* T4 = (__half2*)p;
    cudaGetSymbolAddress(&p, g_hA);   __half2* hA = (__half2*)p;
    cudaGetSymbolAddress(&p, g_hB);   __half2* hB = (__half2*)p;

    cudaMemsetAsync(deg, 0, NN * sizeof(float), 0);
    cudaMemsetAsync(cnt, 0, NN * sizeof(int), 0);
    k_degree<<<(EE + 255) / 256, 256>>>(src, dst);
    k_node<<<(NN + 255) / 256, 256>>>(batch, lmax);
    k_scan<<<1, 1024>>>();
    cudaMemsetAsync(cnt, 0, NN * sizeof(int), 0);
    k_fill<<<(EE + 255) / 256, 256>>>(src, dst, lmax);
    k_xcast<<<(NN * 8 + 255) / 256, 256>>>(x);

    const int PB = 256;
    const int pgrid48 = (NN * 32 + PB - 1) / PB;  // warp per node
    const int pgrid16 = (NN * 8 + PB - 1) / PB;   // 8 lanes per node
    const int mgrid = (NN * 12 + 255) / 256;

    // layer 1 (F_in = 16, T0 = x16)
    k_prop16<false><<<pgrid16, PB>>>(x16, nullptr, T1, 1.0f);
    k_prop16<true><<<pgrid16, PB>>>(T1, x16, T2, 2.0f);
    k_prop16<true><<<pgrid16, PB>>>(T2, T1, T3, 2.0f);
    k_prop16<true><<<pgrid16, PB>>>(T3, T2, T4, 2.0f);
    k_mix<16><<<mgrid, 256>>>(x16, T1, T2, T3, T4, W[0], B[0], hA);

    // layers 2..5 (F_in = 48), ping-pong hA <-> hB
    __half2* cur = hA;
    __half2* nxt = hB;
    for (int l = 1; l < 5; l++) {
        k_prop48<false><<<pgrid48, PB>>>(cur, nullptr, T1, 1.0f);
        k_prop48<true><<<pgrid48, PB>>>(T1, cur, T2, 2.0f);
        k_prop48<true><<<pgrid48, PB>>>(T2, T1, T3, 2.0f);
        k_prop48<true><<<pgrid48, PB>>>(T3, T2, T4, 2.0f);
        k_mix<48><<<mgrid, 256>>>(cur, T1, T2, T3, T4, W[l], B[l], nxt);
        __half2* t = cur; cur = nxt; nxt = t;
    }

    k_pool<<<GG, 480>>>((const __half*)cur, fc1w, fc1b, fc2w, fc2b, out);
}

// round 3
// speedup vs baseline: 1.3123x; 1.0664x over previous
#include <cuda_runtime.h>
#include <cuda_fp16.h>

#define NN 100000
#define EE 3200000
#define GG 100
#define HH 48

// ---------------- device scratch (static: no allocations allowed) ----------------
__device__ float g_deg[NN];
__device__ float g_dis[NN];
__device__ float g_diag[NN];
__device__ int   g_cnt[NN];
__device__ int   g_rowptr[NN + 1];
__device__ int2  g_edge[EE];          // {src, wedge as float bits}, grouped by dst
__device__ __half g_x16[NN * 16];     // layer-1 input in fp16
__device__ __half g_T1[NN * HH];
__device__ __half g_T2[NN * HH];
__device__ __half g_T3[NN * HH];
__device__ __half g_T4[NN * HH];
__device__ __half g_hA[NN * HH];
__device__ __half g_hB[NN * HH];

// ---------------- graph preprocessing ----------------
__global__ void k_degree(const int* __restrict__ src, const int* __restrict__ dst) {
    int e = blockIdx.x * blockDim.x + threadIdx.x;
    if (e >= EE) return;
    atomicAdd(&g_deg[src[e]], 1.0f);
    atomicAdd(&g_cnt[dst[e]], 1);
}

__global__ void k_node(const int* __restrict__ batch, const float* __restrict__ lmax) {
    int n = blockIdx.x * blockDim.x + threadIdx.x;
    if (n >= NN) return;
    float d = g_deg[n];
    g_dis[n] = (d > 0.0f) ? rsqrtf(d) : 0.0f;
    g_diag[n] = 2.0f / lmax[batch[n]] - 1.0f;
}

// single-block exclusive scan of g_cnt -> g_rowptr
__global__ void k_scan() {
    __shared__ int sums[1024];
    const int tid = threadIdx.x;
    const int CH = (NN + 1023) / 1024;
    int start = tid * CH;
    int end = start + CH; if (end > NN) end = NN; if (start > NN) start = NN;
    int s = 0;
    for (int i = start; i < end; i++) s += g_cnt[i];
    sums[tid] = s;
    __syncthreads();
    for (int off = 1; off < 1024; off <<= 1) {
        int v = (tid >= off) ? sums[tid - off] : 0;
        __syncthreads();
        sums[tid] += v;
        __syncthreads();
    }
    int run = sums[tid] - s;
    for (int i = start; i < end; i++) {
        g_rowptr[i] = run;
        run += g_cnt[i];
    }
    if (tid == 1023) g_rowptr[NN] = run;
}

__global__ void k_fill(const int* __restrict__ src, const int* __restrict__ dst,
                       const float* __restrict__ lmax) {
    int e = blockIdx.x * blockDim.x + threadIdx.x;
    if (e >= EE) return;
    int s = src[e], d = dst[e];
    int pos = g_rowptr[d] + atomicAdd(&g_cnt[d], 1);
    float w = -2.0f * g_dis[s] * g_dis[d] / lmax[s / (NN / GG)];
    g_edge[pos] = make_int2(s, __float_as_int(w));
}

__global__ void k_xcast(const float* __restrict__ x) {
    int i = blockIdx.x * blockDim.x + threadIdx.x;   // one half2 per thread
    if (i >= NN * 8) return;
    float2 v = reinterpret_cast<const float2*>(x)[i];
    reinterpret_cast<__half2*>(g_x16)[i] = __floats2half2_rn(v.x, v.y);
}

// ---------------- Chebyshev propagation (fp16 features, fp32 accumulate) -------------
// F = 16: 8 lanes per node, each lane owns one half2 column pair. 8-edge unroll.
template <bool HASPREV>
__global__ void k_prop16(const __half2* __restrict__ tin, const __half2* __restrict__ tprev,
                         __half2* __restrict__ tout, float alpha) {
    int t = blockIdx.x * blockDim.x + threadIdx.x;
    int n = t >> 3;
    if (n >= NN) return;
    int lane = t & 7;
    int beg = g_rowptr[n], end = g_rowptr[n + 1];
    float ax = 0.0f, ay = 0.0f;
    int e = beg;
    for (; e + 8 <= end; e += 8) {
        int2 E[8];
#pragma unroll
        for (int j = 0; j < 8; j++) E[j] = g_edge[e + j];
        __half2 f[8];
#pragma unroll
        for (int j = 0; j < 8; j++) f[j] = tin[E[j].x * 8 + lane];
#pragma unroll
        for (int j = 0; j < 8; j++) {
            float w = __int_as_float(E[j].y);
            float2 v = __half22float2(f[j]);
            ax += w * v.x;
            ay += w * v.y;
        }
    }
    for (; e < end; e++) {
        int2 E0 = g_edge[e];
        float w0 = __int_as_float(E0.y);
        float2 f0 = __half22float2(tin[E0.x * 8 + lane]);
        ax += w0 * f0.x;
        ay += w0 * f0.y;
    }
    float dg = g_diag[n];
    float2 fs = __half22float2(tin[n * 8 + lane]);
    float rx = alpha * (dg * fs.x + ax);
    float ry = alpha * (dg * fs.y + ay);
    if (HASPREV) {
        float2 fp = __half22float2(tprev[n * 8 + lane]);
        rx -= fp.x; ry -= fp.y;
    }
    tout[n * 8 + lane] = __floats2half2_rn(rx, ry);
}

// F = 48: warp per node, lanes 0..23 own half2 column pairs. 8-edge unroll.
template <bool HASPREV>
__global__ void k_prop48(const __half2* __restrict__ tin, const __half2* __restrict__ tprev,
                         __half2* __restrict__ tout, float alpha) {
    int n = (blockIdx.x * blockDim.x + threadIdx.x) >> 5;
    if (n >= NN) return;
    int lane = threadIdx.x & 31;
    bool act = lane < 24;
    int li = act ? lane : 0;
    int beg = g_rowptr[n], end = g_rowptr[n + 1];
    float ax = 0.0f, ay = 0.0f;
    int e = beg;
    for (; e + 8 <= end; e += 8) {
        int2 E[8];
#pragma unroll
        for (int j = 0; j < 8; j++) E[j] = g_edge[e + j];
        __half2 f[8];
#pragma unroll
        for (int j = 0; j < 8; j++) f[j] = tin[E[j].x * 24 + li];
#pragma unroll
        for (int j = 0; j < 8; j++) {
            float w = __int_as_float(E[j].y);
            float2 v = __half22float2(f[j]);
            ax += w * v.x;
            ay += w * v.y;
        }
    }
    for (; e < end; e++) {
        int2 E0 = g_edge[e];
        float w0 = __int_as_float(E0.y);
        float2 f0 = __half22float2(tin[E0.x * 24 + li]);
        ax += w0 * f0.x;
        ay += w0 * f0.y;
    }
    if (act) {
        float dg = g_diag[n];
        float2 fs = __half22float2(tin[n * 24 + lane]);
        float rx = alpha * (dg * fs.x + ax);
        float ry = alpha * (dg * fs.y + ay);
        if (HASPREV) {
            float2 fp = __half22float2(tprev[n * 24 + lane]);
            rx -= fp.x; ry -= fp.y;
        }
        tout[n * 24 + lane] = __floats2half2_rn(rx, ry);
    }
}

// ---------------- fused layer output: h = relu(b + sum_k T_k @ W[k]) ----------------
template <int FIN>
__global__ void k_mix(const __half2* __restrict__ T0, const __half2* __restrict__ T1,
                      const __half2* __restrict__ T2, const __half2* __restrict__ T3,
                      const __half2* __restrict__ T4,
                      const float* __restrict__ W, const float* __restrict__ b,
                      __half2* __restrict__ hout) {
    __shared__ __align__(16) float sW[5 * FIN * 48];
    const int tot = 5 * FIN * 48;
    for (int i = threadIdx.x; i < tot; i += blockDim.x) sW[i] = W[i];
    __syncthreads();
    int gid = blockIdx.x * blockDim.x + threadIdx.x;
    int n = gid / 12;
    int f = (gid % 12) * 4;
    if (n >= NN) return;
    const __half2* Ts[5] = {T0, T1, T2, T3, T4};
    float4 acc = *reinterpret_cast<const float4*>(&b[f]);
#pragma unroll
    for (int k = 0; k < 5; k++) {
        const __half2* T = Ts[k] + n * (FIN / 2);
        const float* wk = &sW[k * FIN * 48 + f];
#pragma unroll
        for (int i2 = 0; i2 < FIN / 2; i2++) {
            float2 v = __half22float2(T[i2]);
            float4 w0 = *reinterpret_cast<const float4*>(wk + (2 * i2) * 48);
            float4 w1 = *reinterpret_cast<const float4*>(wk + (2 * i2 + 1) * 48);
            acc.x += v.x * w0.x + v.y * w1.x;
            acc.y += v.x * w0.y + v.y * w1.y;
            acc.z += v.x * w0.z + v.y * w1.z;
            acc.w += v.x * w0.w + v.y * w1.w;
        }
    }
    acc.x = fmaxf(acc.x, 0.0f);
    acc.y = fmaxf(acc.y, 0.0f);
    acc.z = fmaxf(acc.z, 0.0f);
    acc.w = fmaxf(acc.w, 0.0f);
    hout[n * 24 + f / 2]     = __floats2half2_rn(acc.x, acc.y);
    hout[n * 24 + f / 2 + 1] = __floats2half2_rn(acc.z, acc.w);
}

// ---------------- global_add_pool + MLP head ----------------
__global__ void k_pool(const __half* __restrict__ h,
                       const float* __restrict__ fc1w, const float* __restrict__ fc1b,
                       const float* __restrict__ fc2w, const float* __restrict__ fc2b,
                       float* __restrict__ out) {
    const int g = blockIdx.x;
    const int tid = threadIdx.x;  // 480 threads: r = tid/48 (0..9), f = tid%48
    const int r = tid / 48, f = tid % 48;
    const int base = g * (NN / GG);
    float a = 0.0f;
    for (int n = base + r; n < base + (NN / GG); n += 10) a += __half2float(h[n * 48 + f]);
    __shared__ float red[480];
    __shared__ float pooled[48];
    __shared__ float o1[32];
    red[tid] = a;
    __syncthreads();
    if (tid < 48) {
        float s = 0.0f;
        for (int rr = 0; rr < 10; rr++) s += red[rr * 48 + tid];
        pooled[tid] = s;
    }
    __syncthreads();
    if (tid < 32) {
        float s = fc1b[tid];
        for (int i = 0; i < 48; i++) s += pooled[i] * fc1w[i * 32 + tid];
        o1[tid] = fmaxf(s, 0.0f);
    }
    __syncthreads();
    if (tid == 0) {
        float s = fc2b[0];
        for (int j = 0; j < 32; j++) s += o1[j] * fc2w[j];
        out[g] = s;
    }
}

// ---------------- host launcher ----------------
extern "C" void kernel_launch(void* const* d_in, const int* in_sizes, int n_in,
                              void* d_out, int out_size) {
    const float* x     = (const float*)d_in[0];
    const int*   ei    = (const int*)d_in[1];
    const int*   src   = ei;
    const int*   dst   = ei + EE;
    const int*   batch = (const int*)d_in[2];
    const float* lmax  = (const float*)d_in[3];
    const float* W[5]  = {(const float*)d_in[4], (const float*)d_in[6], (const float*)d_in[8],
                          (const float*)d_in[10], (const float*)d_in[12]};
    const float* B[5]  = {(const float*)d_in[5], (const float*)d_in[7], (const float*)d_in[9],
                          (const float*)d_in[11], (const float*)d_in[13]};
    const float* fc1w = (const float*)d_in[14];
    const float* fc1b = (const float*)d_in[15];
    const float* fc2w = (const float*)d_in[16];
    const float* fc2b = (const float*)d_in[17];
    float* out = (float*)d_out;

    void* p;
    cudaGetSymbolAddress(&p, g_deg);  float* deg = (float*)p;
    cudaGetSymbolAddress(&p, g_cnt);  int* cnt = (int*)p;
    cudaGetSymbolAddress(&p, g_x16);  __half2* x16 = (__half2*)p;
    cudaGetSymbolAddress(&p, g_T1);   __half2* T1 = (__half2*)p;
    cudaGetSymbolAddress(&p, g_T2);   __half2* T2 = (__half2*)p;
    cudaGetSymbolAddress(&p, g_T3);   __half2* T3 = (__half2*)p;
    cudaGetSymbolAddress(&p, g_T4);   __half2* T4 = (__half2*)p;
    cudaGetSymbolAddress(&p, g_hA);   __half2* hA = (__half2*)p;
    cudaGetSymbolAddress(&p, g_hB);   __half2* hB = (__half2*)p;

    cudaMemsetAsync(deg, 0, NN * sizeof(float), 0);
    cudaMemsetAsync(cnt, 0, NN * sizeof(int), 0);
    k_degree<<<(EE + 255) / 256, 256>>>(src, dst);
    k_node<<<(NN + 255) / 256, 256>>>(batch, lmax);
    k_scan<<<1, 1024>>>();
    cudaMemsetAsync(cnt, 0, NN * sizeof(int), 0);
    k_fill<<<(EE + 255) / 256, 256>>>(src, dst, lmax);
    k_xcast<<<(NN * 8 + 255) / 256, 256>>>(x);

    const int PB = 256;
    const int pgrid48 = (NN * 32 + PB - 1) / PB;  // warp per node
    const int pgrid16 = (NN * 8 + PB - 1) / PB;   // 8 lanes per node
    const int mgrid = (NN * 12 + 255) / 256;

    // layer 1 (F_in = 16, T0 = x16)
    k_prop16<false><<<pgrid16, PB>>>(x16, nullptr, T1, 1.0f);
    k_prop16<true><<<pgrid16, PB>>>(T1, x16, T2, 2.0f);
    k_prop16<true><<<pgrid16, PB>>>(T2, T1, T3, 2.0f);
    k_prop16<true><<<pgrid16, PB>>>(T3, T2, T4, 2.0f);
    k_mix<16><<<mgrid, 256>>>(x16, T1, T2, T3, T4, W[0], B[0], hA);

    // layers 2..5 (F_in = 48), ping-pong hA <-> hB
    __half2* cur = hA;
    __half2* nxt = hB;
    for (int l = 1; l < 5; l++) {
        k_prop48<false><<<pgrid48, PB>>>(cur, nullptr, T1, 1.0f);
        k_prop48<true><<<pgrid48, PB>>>(T1, cur, T2, 2.0f);
        k_prop48<true><<<pgrid48, PB>>>(T2, T1, T3, 2.0f);
        k_prop48<true><<<pgrid48, PB>>>(T3, T2, T4, 2.0f);
        k_mix<48><<<mgrid, 256>>>(cur, T1, T2, T3, T4, W[l], B[l], nxt);
        __half2* t = cur; cur = nxt; nxt = t;
    }

    k_pool<<<GG, 480>>>((const __half*)cur, fc1w, fc1b, fc2w, fc2b, out);
}

// round 5
// speedup vs baseline: 1.3871x; 1.0570x over previous
#include <cuda_runtime.h>
#include <cuda_fp16.h>

#define NN 100000
#define EE 3200000
#define GG 100
#define HH 48

// ---------------- device scratch ----------------
__device__ int   g_degi[NN];
__device__ float g_dis[NN];
__device__ float g_diag[NN];
__device__ int   g_cnt[NN];
__device__ int   g_rowptr[NN + 1];
__device__ int2  g_edge[EE];          // {src, weight as half2 (broadcast) bits}, grouped by dst
__device__ __half g_x16[NN * 16];
__device__ __half g_T1[NN * HH];
__device__ __half g_T2[NN * HH];
__device__ __half g_T3[NN * HH];
__device__ __half g_T4[NN * HH];
__device__ __half g_hA[NN * HH];
__device__ __half g_hB[NN * HH];

// ---------------- graph preprocessing ----------------
__global__ void k_degree(const int* __restrict__ src, const int* __restrict__ dst) {
    int e = blockIdx.x * blockDim.x + threadIdx.x;
    if (e >= EE) return;
    atomicAdd(&g_degi[src[e]], 1);
    atomicAdd(&g_cnt[dst[e]], 1);
}

__global__ void k_node(const int* __restrict__ batch, const float* __restrict__ lmax) {
    int n = blockIdx.x * blockDim.x + threadIdx.x;
    if (n >= NN) return;
    float d = (float)g_degi[n];
    g_dis[n] = (d > 0.0f) ? rsqrtf(d) : 0.0f;
    g_diag[n] = 2.0f / lmax[batch[n]] - 1.0f;
}

// single-block exclusive scan of g_cnt -> g_rowptr
__global__ void k_scan() {
    __shared__ int sums[1024];
    const int tid = threadIdx.x;
    const int CH = (NN + 1023) / 1024;
    int start = tid * CH;
    int end = start + CH; if (end > NN) end = NN; if (start > NN) start = NN;
    int s = 0;
    for (int i = start; i < end; i++) s += g_cnt[i];
    sums[tid] = s;
    __syncthreads();
    for (int off = 1; off < 1024; off <<= 1) {
        int v = (tid >= off) ? sums[tid - off] : 0;
        __syncthreads();
        sums[tid] += v;
        __syncthreads();
    }
    int run = sums[tid] - s;
    for (int i = start; i < end; i++) {
        g_rowptr[i] = run;
        run += g_cnt[i];
    }
    if (tid == 1023) g_rowptr[NN] = run;
}

__global__ void k_fill(const int* __restrict__ src, const int* __restrict__ dst,
                       const float* __restrict__ lmax) {
    int e = blockIdx.x * blockDim.x + threadIdx.x;
    if (e >= EE) return;
    int s = src[e], d = dst[e];
    int pos = g_rowptr[d] + atomicAdd(&g_cnt[d], 1);
    float w = -2.0f * g_dis[s] * g_dis[d] / lmax[s / (NN / GG)];
    __half2 w2 = __half2half2(__float2half_rn(w));
    g_edge[pos] = make_int2(s, *reinterpret_cast<const int*>(&w2));
}

__global__ void k_xcast(const float* __restrict__ x) {
    int i = blockIdx.x * blockDim.x + threadIdx.x;
    if (i >= NN * 8) return;
    float2 v = reinterpret_cast<const float2*>(x)[i];
    reinterpret_cast<__half2*>(g_x16)[i] = __floats2half2_rn(v.x, v.y);
}

// ---------------- Chebyshev propagation (fp16 features, half2 FMA accumulate) --------
// F = 16: 8 lanes per node (4 nodes/warp), each lane owns one half2 column pair.
template <bool HASPREV>
__global__ void k_prop16(const __half2* __restrict__ tin, const __half2* __restrict__ tprev,
                         __half2* __restrict__ tout, float alpha) {
    int t = blockIdx.x * blockDim.x + threadIdx.x;
    int n = t >> 3;
    if (n >= NN) return;
    int lane = t & 7;
    int beg = g_rowptr[n], end = g_rowptr[n + 1];
    __half2 acc = __float2half2_rn(0.0f);
    int e = beg;
    for (; e + 8 <= end; e += 8) {
        int2 E[8];
#pragma unroll
        for (int j = 0; j < 8; j++) E[j] = g_edge[e + j];
        __half2 f[8];
#pragma unroll
        for (int j = 0; j < 8; j++) f[j] = tin[E[j].x * 8 + lane];
#pragma unroll
        for (int j = 0; j < 8; j++)
            acc = __hfma2(*reinterpret_cast<const __half2*>(&E[j].y), f[j], acc);
    }
    for (; e < end; e++) {
        int2 E0 = g_edge[e];
        __half2 f0 = tin[E0.x * 8 + lane];
        acc = __hfma2(*reinterpret_cast<const __half2*>(&E0.y), f0, acc);
    }
    float2 a = __half22float2(acc);
    float dg = g_diag[n];
    float2 fs = __half22float2(tin[n * 8 + lane]);
    float rx = alpha * (dg * fs.x + a.x);
    float ry = alpha * (dg * fs.y + a.y);
    if (HASPREV) {
        float2 fp = __half22float2(tprev[n * 8 + lane]);
        rx -= fp.x; ry -= fp.y;
    }
    tout[n * 8 + lane] = __floats2half2_rn(rx, ry);
}

// F = 48: warp per node, lanes 0..23 own half2 column pairs.
template <bool HASPREV>
__global__ void k_prop48(const __half2* __restrict__ tin, const __half2* __restrict__ tprev,
                         __half2* __restrict__ tout, float alpha) {
    int n = (blockIdx.x * blockDim.x + threadIdx.x) >> 5;
    if (n >= NN) return;
    int lane = threadIdx.x & 31;
    bool act = lane < 24;
    int li = act ? lane : 0;
    int beg = g_rowptr[n], end = g_rowptr[n + 1];
    __half2 acc = __float2half2_rn(0.0f);
    int e = beg;
    for (; e + 8 <= end; e += 8) {
        int2 E[8];
#pragma unroll
        for (int j = 0; j < 8; j++) E[j] = g_edge[e + j];
        __half2 f[8];
#pragma unroll
        for (int j = 0; j < 8; j++) f[j] = tin[E[j].x * 24 + li];
#pragma unroll
        for (int j = 0; j < 8; j++)
            acc = __hfma2(*reinterpret_cast<const __half2*>(&E[j].y), f[j], acc);
    }
    for (; e < end; e++) {
        int2 E0 = g_edge[e];
        __half2 f0 = tin[E0.x * 24 + li];
        acc = __hfma2(*reinterpret_cast<const __half2*>(&E0.y), f0, acc);
    }
    if (act) {
        float2 a = __half22float2(acc);
        float dg = g_diag[n];
        float2 fs = __half22float2(tin[n * 24 + lane]);
        float rx = alpha * (dg * fs.x + a.x);
        float ry = alpha * (dg * fs.y + a.y);
        if (HASPREV) {
            float2 fp = __half22float2(tprev[n * 24 + lane]);
            rx -= fp.x; ry -= fp.y;
        }
        tout[n * 24 + lane] = __floats2half2_rn(rx, ry);
    }
}

// ---------------- fused layer output: h = relu(b + sum_k T_k @ W[k]) ----------------
template <int FIN>
__global__ void k_mix(const __half2* __restrict__ T0, const __half2* __restrict__ T1,
                      const __half2* __restrict__ T2, const __half2* __restrict__ T3,
                      const __half2* __restrict__ T4,
                      const float* __restrict__ W, const float* __restrict__ b,
                      __half2* __restrict__ hout) {
    __shared__ __align__(16) float sW[5 * FIN * 48];
    const int tot = 5 * FIN * 48;
    for (int i = threadIdx.x; i < tot; i += blockDim.x) sW[i] = W[i];
    __syncthreads();
    int gid = blockIdx.x * blockDim.x + threadIdx.x;
    int n = gid / 12;
    int f = (gid % 12) * 4;
    if (n >= NN) return;
    const __half2* Ts[5] = {T0, T1, T2, T3, T4};
    float4 acc = *reinterpret_cast<const float4*>(&b[f]);
#pragma unroll
    for (int k = 0; k < 5; k++) {
        const __half2* T = Ts[k] + n * (FIN / 2);
        const float* wk = &sW[k * FIN * 48 + f];
#pragma unroll
        for (int i2 = 0; i2 < FIN / 2; i2++) {
            float2 v = __half22float2(T[i2]);
            float4 w0 = *reinterpret_cast<const float4*>(wk + (2 * i2) * 48);
            float4 w1 = *reinterpret_cast<const float4*>(wk + (2 * i2 + 1) * 48);
            acc.x += v.x * w0.x + v.y * w1.x;
            acc.y += v.x * w0.y + v.y * w1.y;
            acc.z += v.x * w0.z + v.y * w1.z;
            acc.w += v.x * w0.w + v.y * w1.w;
        }
    }
    acc.x = fmaxf(acc.x, 0.0f);
    acc.y = fmaxf(acc.y, 0.0f);
    acc.z = fmaxf(acc.z, 0.0f);
    acc.w = fmaxf(acc.w, 0.0f);
    hout[n * 24 + f / 2]     = __floats2half2_rn(acc.x, acc.y);
    hout[n * 24 + f / 2 + 1] = __floats2half2_rn(acc.z, acc.w);
}

// ---------------- global_add_pool + MLP head ----------------
__global__ void k_pool(const __half* __restrict__ h,
                       const float* __restrict__ fc1w, const float* __restrict__ fc1b,
                       const float* __restrict__ fc2w, const float* __restrict__ fc2b,
                       float* __restrict__ out) {
    const int g = blockIdx.x;
    const int tid = threadIdx.x;
    const int r = tid / 48, f = tid % 48;
    const int base = g * (NN / GG);
    float a = 0.0f;
    for (int n = base + r; n < base + (NN / GG); n += 10) a += __half2float(h[n * 48 + f]);
    __shared__ float red[480];
    __shared__ float pooled[48];
    __shared__ float o1[32];
    red[tid] = a;
    __syncthreads();
    if (tid < 48) {
        float s = 0.0f;
        for (int rr = 0; rr < 10; rr++) s += red[rr * 48 + tid];
        pooled[tid] = s;
    }
    __syncthreads();
    if (tid < 32) {
        float s = fc1b[tid];
        for (int i = 0; i < 48; i++) s += pooled[i] * fc1w[i * 32 + tid];
        o1[tid] = fmaxf(s, 0.0f);
    }
    __syncthreads();
    if (tid == 0) {
        float s = fc2b[0];
        for (int j = 0; j < 32; j++) s += o1[j] * fc2w[j];
        out[g] = s;
    }
}

// ---------------- host launcher ----------------
extern "C" void kernel_launch(void* const* d_in, const int* in_sizes, int n_in,
                              void* d_out, int out_size) {
    const float* x     = (const float*)d_in[0];
    const int*   ei    = (const int*)d_in[1];
    const int*   src   = ei;
    const int*   dst   = ei + EE;
    const int*   batch = (const int*)d_in[2];
    const float* lmax  = (const float*)d_in[3];
    const float* W[5]  = {(const float*)d_in[4], (const float*)d_in[6], (const float*)d_in[8],
                          (const float*)d_in[10], (const float*)d_in[12]};
    const float* B[5]  = {(const float*)d_in[5], (const float*)d_in[7], (const float*)d_in[9],
                          (const float*)d_in[11], (const float*)d_in[13]};
    const float* fc1w = (const float*)d_in[14];
    const float* fc1b = (const float*)d_in[15];
    const float* fc2w = (const float*)d_in[16];
    const float* fc2b = (const float*)d_in[17];
    float* out = (float*)d_out;

    void* p;
    cudaGetSymbolAddress(&p, g_degi); int* degi = (int*)p;
    cudaGetSymbolAddress(&p, g_cnt);  int* cnt = (int*)p;
    cudaGetSymbolAddress(&p, g_x16);  __half2* x16 = (__half2*)p;
    cudaGetSymbolAddress(&p, g_T1);   __half2* T1 = (__half2*)p;
    cudaGetSymbolAddress(&p, g_T2);   __half2* T2 = (__half2*)p;
    cudaGetSymbolAddress(&p, g_T3);   __half2* T3 = (__half2*)p;
    cudaGetSymbolAddress(&p, g_T4);   __half2* T4 = (__half2*)p;
    cudaGetSymbolAddress(&p, g_hA);   __half2* hA = (__half2*)p;
    cudaGetSymbolAddress(&p, g_hB);   __half2* hB = (__half2*)p;

    cudaMemsetAsync(degi, 0, NN * sizeof(int), 0);
    cudaMemsetAsync(cnt, 0, NN * sizeof(int), 0);
    k_degree<<<(EE + 255) / 256, 256>>>(src, dst);
    k_node<<<(NN + 255) / 256, 256>>>(batch, lmax);
    k_scan<<<1, 1024>>>();
    cudaMemsetAsync(cnt, 0, NN * sizeof(int), 0);
    k_fill<<<(EE + 255) / 256, 256>>>(src, dst, lmax);
    k_xcast<<<(NN * 8 + 255) / 256, 256>>>(x);

    const int PB = 256;
    const int pgrid48 = (NN * 32 + PB - 1) / PB;
    const int pgrid16 = (NN * 8 + PB - 1) / PB;
    const int mgrid = (NN * 12 + 255) / 256;

    // layer 1 (F_in = 16, T0 = x16)
    k_prop16<false><<<pgrid16, PB>>>(x16, nullptr, T1, 1.0f);
    k_prop16<true><<<pgrid16, PB>>>(T1, x16, T2, 2.0f);
    k_prop16<true><<<pgrid16, PB>>>(T2, T1, T3, 2.0f);
    k_prop16<true><<<pgrid16, PB>>>(T3, T2, T4, 2.0f);
    k_mix<16><<<mgrid, 256>>>(x16, T1, T2, T3, T4, W[0], B[0], hA);

    // layers 2..5 (F_in = 48), ping-pong hA <-> hB
    __half2* cur = hA;
    __half2* nxt = hB;
    for (int l = 1; l < 5; l++) {
        k_prop48<false><<<pgrid48, PB>>>(cur, nullptr, T1, 1.0f);
        k_prop48<true><<<pgrid48, PB>>>(T1, cur, T2, 2.0f);
        k_prop48<true><<<pgrid48, PB>>>(T2, T1, T3, 2.0f);
        k_prop48<true><<<pgrid48, PB>>>(T3, T2, T4, 2.0f);
        k_mix<48><<<mgrid, 256>>>(cur, T1, T2, T3, T4, W[l], B[l], nxt);
        __half2* t = cur; cur = nxt; nxt = t;
    }

    k_pool<<<GG, 480>>>((const __half*)cur, fc1w, fc1b, fc2w, fc2b, out);
}